// round 9
// baseline (speedup 1.0000x reference)
#include <cuda_runtime.h>
#include <math.h>
#include <stdint.h>

#define NGRAPH 32
#define NNODE  1024
#define CDIM   64
#define KTOP   16
#define NROWS  (NGRAPH * NNODE)            // 32768
#define OUT_ELEMS (NROWS * CDIM)           // 2097152
#define ROWS_OFF  OUT_ELEMS
#define COLS_OFF  (OUT_ELEMS + NROWS * KTOP)

__device__ float g_sq[NROWS];

// ---------------------------------------------------------------------------
// Encoder + fused row squared-norms.  4x4 register tile, 64-row blocks.
// ---------------------------------------------------------------------------
#define ENC_WT   0                          // [64][132] floats = 8448
#define ENC_X    8448                       // [64][128] floats = 8192
#define ENC_TOTF 16640
#define ENC_BYTES (ENC_TOTF * 4)

__global__ void __launch_bounds__(256) enc_kernel(const float* __restrict__ x,
                                                  const float* __restrict__ W,
                                                  const float* __restrict__ b,
                                                  float* __restrict__ out) {
    extern __shared__ float esm[];
    float* sWt = esm + ENC_WT;
    float* sX  = esm + ENC_X;
    int tid = threadIdx.x;
    int i0 = blockIdx.x * 64;

    for (int idx = tid; idx < 128 * 64; idx += 256) {
        int k = idx >> 6, c = idx & 63;
        sWt[c * 132 + k] = W[idx];
    }
    for (int idx = tid; idx < 64 * 128 / 4; idx += 256) {
        ((float4*)sX)[idx] = ((const float4*)(x + (size_t)i0 * 128))[idx];
    }
    __syncthreads();

    int cgrp = tid & 15;
    int rgrp = tid >> 4;
    float acc[4][4];
#pragma unroll
    for (int rr = 0; rr < 4; rr++)
#pragma unroll
        for (int cc = 0; cc < 4; cc++) acc[rr][cc] = 0.f;

#pragma unroll
    for (int k4 = 0; k4 < 32; k4++) {
        float4 wv[4];
#pragma unroll
        for (int cc = 0; cc < 4; cc++)
            wv[cc] = *(const float4*)(sWt + (cgrp + 16 * cc) * 132 + k4 * 4);
#pragma unroll
        for (int rr = 0; rr < 4; rr++) {
            float4 xv = *(const float4*)(sX + (rgrp * 4 + rr) * 128 + k4 * 4);
#pragma unroll
            for (int cc = 0; cc < 4; cc++) {
                acc[rr][cc] += xv.x * wv[cc].x + xv.y * wv[cc].y
                             + xv.z * wv[cc].z + xv.w * wv[cc].w;
            }
        }
    }

    float bb[4];
#pragma unroll
    for (int cc = 0; cc < 4; cc++) bb[cc] = b[cgrp + 16 * cc];

    float sqp[4] = {0.f, 0.f, 0.f, 0.f};
#pragma unroll
    for (int rr = 0; rr < 4; rr++) {
        int r = i0 + rgrp * 4 + rr;
#pragma unroll
        for (int cc = 0; cc < 4; cc++) {
            float val = acc[rr][cc] + bb[cc];
            out[(size_t)r * 64 + cgrp + 16 * cc] = val;
            sqp[rr] += val * val;
        }
    }
#pragma unroll
    for (int rr = 0; rr < 4; rr++) {
#pragma unroll
        for (int o = 8; o; o >>= 1) sqp[rr] += __shfl_xor_sync(0xffffffffu, sqp[rr], o);
    }
    if (cgrp == 0) {
#pragma unroll
        for (int rr = 0; rr < 4; rr++) g_sq[i0 + rgrp * 4 + rr] = sqp[rr];
    }
}

// ---------------------------------------------------------------------------
// JAX threefry2x32, key (0,1), partitionable counter mode (verified R3).
// ---------------------------------------------------------------------------
__device__ __forceinline__ uint32_t threefry_bits_k01(uint32_t e) {
    const uint32_t ks0 = 0u, ks1 = 1u, ks2 = 0x1BD11BDBu;
    uint32_t x0 = 0u + ks0;
    uint32_t x1 = e + ks1;
#define TF_ROUND(r) { x0 += x1; x1 = __funnelshift_l(x1, x1, (r)); x1 ^= x0; }
    TF_ROUND(13) TF_ROUND(15) TF_ROUND(26) TF_ROUND(6)
    x0 += ks1; x1 += ks2 + 1u;
    TF_ROUND(17) TF_ROUND(29) TF_ROUND(16) TF_ROUND(24)
    x0 += ks2; x1 += ks0 + 2u;
    TF_ROUND(13) TF_ROUND(15) TF_ROUND(26) TF_ROUND(6)
    x0 += ks0; x1 += ks1 + 3u;
    TF_ROUND(17) TF_ROUND(29) TF_ROUND(16) TF_ROUND(24)
    x0 += ks1; x1 += ks2 + 4u;
    TF_ROUND(13) TF_ROUND(15) TF_ROUND(26) TF_ROUND(6)
    x0 += ks2; x1 += ks0 + 5u;
#undef TF_ROUND
    return x0 ^ x1;
}

// Packed dual-FMA (sm_103a f32x2 pipe)
__device__ __forceinline__ void ffma2(unsigned long long& d,
                                      unsigned long long a,
                                      unsigned long long b) {
    asm("fma.rn.f32x2 %0, %1, %2, %0;" : "+l"(d) : "l"(a), "l"(b));
}

// ---------------------------------------------------------------------------
// Fused: pairwise dist + logits + gumbel + top-16 per row.
// Block = (graph g, 32-row i-strip), 256 threads, grid (32, 32), 4 blocks/SM.
// Register-prefetch double-buffered sB; warp-parallel cooperative merge.
// ---------------------------------------------------------------------------
#define TI 32
#define TJ 64
#define NT (NNODE / TJ)
#define CAP 32
#define SSTRIDE 68    // floats; odd 16B-unit stride -> conflict-free LDS.128
#define THR0 2.8f     // phantom init threshold; P(any row final 16th < 2.8) ~ 6e-5
#define LGMAX 1.001f

// shared layout in floats
#define SM_SA     0                        // [32][68]  = 2176
#define SM_SB     2176                     // [64][68]  = 4352
#define SM_SQI    6528                     // [32]
#define SM_SQJ    6560                     // [64]
#define SM_THR    6624                     // [32]
#define SM_CUTB   6656                     // [32] uint
#define SM_TOPV   6688                     // [32][16]  = 512
#define SM_CANDV  7200                     // [32][32]  = 1024
#define SM_CANDI  8224                     // [32][32] int
#define SM_TOPI   9248                     // [32][16] int
#define SM_CNT    9760                     // [32] int
#define SM_TOTALF 9792
#define SM_BYTES  (SM_TOTALF * 4)          // 39168 B -> 4 blocks/SM

__device__ __forceinline__ uint32_t cut_bits_from_thr(float thr) {
    float fcut = __expf(-__expf(-(thr - LGMAX))) - 2e-7f;
    return __float_as_uint(1.0f + fcut);
}

__global__ void __launch_bounds__(256, 4) dgm_kernel(float* __restrict__ buf,
                                                     const float* __restrict__ tptr) {
    extern __shared__ float sm[];
    float* sA    = sm + SM_SA;
    float* sB    = sm + SM_SB;
    float* sqI   = sm + SM_SQI;
    float* sqJ   = sm + SM_SQJ;
    float* thr   = sm + SM_THR;
    uint32_t* cutb = (uint32_t*)(sm + SM_CUTB);
    float* topV  = sm + SM_TOPV;
    float* candV = sm + SM_CANDV;
    int*   candI = (int*)(sm + SM_CANDI);
    int*   topI  = (int*)(sm + SM_TOPI);
    int*   cnt   = (int*)(sm + SM_CNT);

    const float* h = buf;
    int tid = threadIdx.x;
    int g   = blockIdx.x;
    int i0  = blockIdx.y * TI;
    int gbase = g * NNODE;

    // ---- init: sA strip, state, and tile-0 sB ----
    for (int idx = tid; idx < TI * 16; idx += 256) {
        int r = idx >> 4, k4 = idx & 15;
        *(float4*)(sA + r * SSTRIDE + k4 * 4) =
            ((const float4*)(h + (size_t)(gbase + i0 + r) * 64))[k4];
    }
    {   // tile 0 sB: 64 rows x 16 float4 = 1024 float4 / 256 threads = 4 each
        int r = tid >> 2, k4g = (tid & 3) * 4;
#pragma unroll
        for (int u = 0; u < 4; u++) {
            *(float4*)(sB + r * SSTRIDE + (k4g + u) * 4) =
                ((const float4*)(h + (size_t)(gbase + r) * 64))[k4g + u];
        }
    }
    if (tid < TI) {
        sqI[tid] = g_sq[gbase + i0 + tid];
        thr[tid] = THR0;
        cutb[tid] = cut_bits_from_thr(THR0);
        cnt[tid] = 0;
    }
    if (tid < TJ) sqJ[tid] = g_sq[gbase + tid];
    for (int idx = tid; idx < TI * KTOP; idx += 256) { topV[idx] = -INFINITY; topI[idx] = 0; }

    float nT = -(*tptr);
    int tx = tid & 31;      // j-cols: tx + 32*jj, jj in {0,1}
    int ty = tid >> 5;      // i-rows: ty*4 + ii
    int pr  = tid >> 2;              // prefetch row, 0..63
    int pk4 = (tid & 3) * 4;         // prefetch k4 group base

    __syncthreads();

    for (int jt = 0; jt < NT; jt++) {
        int j0 = jt * TJ;

        // ---- issue prefetch LDGs for next tile (latency hidden by compute) ----
        float4 pv[4];
        float sqnext = 0.f;
        if (jt + 1 < NT) {
            const float4* src = (const float4*)(h + (size_t)(gbase + (j0 + TJ) + pr) * 64);
#pragma unroll
            for (int u = 0; u < 4; u++) pv[u] = src[pk4 + u];
            if (tid < TJ) sqnext = g_sq[gbase + j0 + TJ + tid];
        }

        // ---- 4x2 register-tiled dots, packed f32x2 FMA ----
        unsigned long long acc2[4][2];
#pragma unroll
        for (int ii = 0; ii < 4; ii++) { acc2[ii][0] = 0ull; acc2[ii][1] = 0ull; }

        const float* pA = sA + (ty * 4) * SSTRIDE;
        const float* pB = sB + tx * SSTRIDE;
#pragma unroll
        for (int k4 = 0; k4 < 16; k4++) {
            ulonglong2 b0 = *(const ulonglong2*)(pB + k4 * 4);
            ulonglong2 b1 = *(const ulonglong2*)(pB + 32 * SSTRIDE + k4 * 4);
#pragma unroll
            for (int ii = 0; ii < 4; ii++) {
                ulonglong2 a = *(const ulonglong2*)(pA + ii * SSTRIDE + k4 * 4);
                ffma2(acc2[ii][0], a.x, b0.x);
                ffma2(acc2[ii][0], a.y, b0.y);
                ffma2(acc2[ii][1], a.x, b1.x);
                ffma2(acc2[ii][1], a.y, b1.y);
            }
        }

        // ---- per-row scalars ----
        float thrR[4], sqi[4], sqj[2];
        uint32_t cutM[4];
#pragma unroll
        for (int ii = 0; ii < 4; ii++) {
            thrR[ii] = thr[ty * 4 + ii];
            sqi[ii]  = sqI[ty * 4 + ii];
            cutM[ii] = cutb[ty * 4 + ii] & 0x007fffffu;
        }
        sqj[0] = sqJ[tx];
        sqj[1] = sqJ[32 + tx];

        uint32_t e0 = ((uint32_t)g << 20) + ((uint32_t)(i0 + ty * 4) << 10)
                      + (uint32_t)(j0 + tx);

        // ---- batched hashes + filter ----
        uint32_t bts[8];
#pragma unroll
        for (int u = 0; u < 8; u++) {
            int ii = u >> 1, jj = u & 1;
            bts[u] = threefry_bits_k01(e0 + ((uint32_t)ii << 10) + ((uint32_t)jj << 5));
        }
#pragma unroll
        for (int u = 0; u < 8; u++) {
            int ii = u >> 1, jj = u & 1;
            uint32_t mant = bts[u] >> 9;
            if (mant > cutM[ii]) {
                int li = ty * 4 + ii;
                unsigned long long av = acc2[ii][jj];
                float dot = __uint_as_float((uint32_t)av)
                          + __uint_as_float((uint32_t)(av >> 32));
                float f   = __uint_as_float(mant | 0x3f800000u) - 1.0f;
                float gum = -__logf(-log1pf(f - 1.0f));
                float s   = __fadd_rn(sqi[ii], sqj[jj]);
                float d   = __fadd_rn(s, -__fmul_rn(2.0f, dot));
                float lg  = __expf(__fmul_rn(nT, d));
                float v   = lg + gum;
                if (v > thrR[ii]) {
                    int p = atomicAdd(&cnt[li], 1);
                    if (p < CAP) {
                        candV[li * CAP + p] = v;
                        candI[li * CAP + p] = j0 + jj * 32 + tx;
                    }
                }
            }
        }
        __syncthreads();   // cands complete, everyone done reading sB

        // ---- store prefetched tile (overlaps merge below) ----
        if (jt + 1 < NT) {
#pragma unroll
            for (int u = 0; u < 4; u++)
                *(float4*)(sB + pr * SSTRIDE + (pk4 + u) * 4) = pv[u];
            if (tid < TJ) sqJ[tid] = sqnext;
        }

        // ---- warp-parallel cooperative merge: warp w owns rows 4w..4w+3 ----
        {
            int w = ty, lane = tx;
#pragma unroll
            for (int rr = 0; rr < 4; rr++) {
                int r = w * 4 + rr;
                int c = min(cnt[r], CAP);
                float vv = (lane < c) ? candV[r * CAP + lane] : -INFINITY;
                int   vi = (lane < c) ? candI[r * CAP + lane] : 0;
                float t15 = topV[r * KTOP + KTOP - 1];
                while (__any_sync(0xffffffffu, vv > t15)) {
                    float m = vv;
#pragma unroll
                    for (int o = 16; o; o >>= 1)
                        m = fmaxf(m, __shfl_xor_sync(0xffffffffu, m, o));
                    unsigned msk = __ballot_sync(0xffffffffu, vv == m);
                    int src = __ffs(msk) - 1;
                    float mv = __shfl_sync(0xffffffffu, vv, src);
                    int   mi = __shfl_sync(0xffffffffu, vi, src);
                    if (lane == src) vv = -INFINITY;
                    if (lane == 0 && mv > topV[r * KTOP + KTOP - 1]) {
                        int p = KTOP - 1;
                        while (p > 0 && topV[r * KTOP + p - 1] < mv) {
                            topV[r * KTOP + p] = topV[r * KTOP + p - 1];
                            topI[r * KTOP + p] = topI[r * KTOP + p - 1];
                            p--;
                        }
                        topV[r * KTOP + p] = mv;
                        topI[r * KTOP + p] = mi;
                    }
                    __syncwarp();
                    t15 = topV[r * KTOP + KTOP - 1];
                }
                if (lane == 0) {
                    cnt[r] = 0;
                    float nthr = fmaxf(t15, THR0);
                    thr[r] = nthr;
                    cutb[r] = cut_bits_from_thr(nthr);
                }
            }
        }
        __syncthreads();   // sB stored + merge done
    }

    // ---- write edges (indices as float) ----
    if (tid < TI) {
        int grow = gbase + i0 + tid;
        size_t base = (size_t)grow * KTOP;
        float rowv = (float)grow;
#pragma unroll
        for (int k = 0; k < KTOP; k++) {
            buf[ROWS_OFF + base + k] = rowv;
            buf[COLS_OFF + base + k] = (float)(gbase + topI[tid * KTOP + k]);
        }
    }
}

// ---------------------------------------------------------------------------
extern "C" void kernel_launch(void* const* d_in, const int* in_sizes, int n_in,
                              void* d_out, int out_size) {
    const float* x    = (const float*)d_in[0];
    const float* W    = (const float*)d_in[1];
    const float* b    = (const float*)d_in[2];
    const float* temp = (const float*)d_in[3];
    float* out = (float*)d_out;

    cudaFuncSetAttribute(enc_kernel, cudaFuncAttributeMaxDynamicSharedMemorySize, ENC_BYTES);
    enc_kernel<<<NROWS / 64, 256, ENC_BYTES>>>(x, W, b, out);
    cudaFuncSetAttribute(dgm_kernel, cudaFuncAttributeMaxDynamicSharedMemorySize, SM_BYTES);
    dgm_kernel<<<dim3(NGRAPH, NNODE / TI), 256, SM_BYTES>>>(out, temp);
}

// round 10
// speedup vs baseline: 2.2681x; 2.2681x over previous
#include <cuda_runtime.h>
#include <math.h>
#include <stdint.h>

#define NGRAPH 32
#define NNODE  1024
#define CDIM   64
#define KTOP   16
#define NROWS  (NGRAPH * NNODE)            // 32768
#define OUT_ELEMS (NROWS * CDIM)           // 2097152
#define ROWS_OFF  OUT_ELEMS
#define COLS_OFF  (OUT_ELEMS + NROWS * KTOP)

__device__ float g_sq[NROWS];

// ---------------------------------------------------------------------------
// Encoder + fused row squared-norms.  4x4 register tile, 64-row blocks.
// ---------------------------------------------------------------------------
#define ENC_WT   0
#define ENC_X    8448
#define ENC_TOTF 16640
#define ENC_BYTES (ENC_TOTF * 4)

__global__ void __launch_bounds__(256) enc_kernel(const float* __restrict__ x,
                                                  const float* __restrict__ W,
                                                  const float* __restrict__ b,
                                                  float* __restrict__ out) {
    extern __shared__ float esm[];
    float* sWt = esm + ENC_WT;
    float* sX  = esm + ENC_X;
    int tid = threadIdx.x;
    int i0 = blockIdx.x * 64;

    for (int idx = tid; idx < 128 * 64; idx += 256) {
        int k = idx >> 6, c = idx & 63;
        sWt[c * 132 + k] = W[idx];
    }
    for (int idx = tid; idx < 64 * 128 / 4; idx += 256) {
        ((float4*)sX)[idx] = ((const float4*)(x + (size_t)i0 * 128))[idx];
    }
    __syncthreads();

    int cgrp = tid & 15;
    int rgrp = tid >> 4;
    float acc[4][4];
#pragma unroll
    for (int rr = 0; rr < 4; rr++)
#pragma unroll
        for (int cc = 0; cc < 4; cc++) acc[rr][cc] = 0.f;

#pragma unroll
    for (int k4 = 0; k4 < 32; k4++) {
        float4 wv[4];
#pragma unroll
        for (int cc = 0; cc < 4; cc++)
            wv[cc] = *(const float4*)(sWt + (cgrp + 16 * cc) * 132 + k4 * 4);
#pragma unroll
        for (int rr = 0; rr < 4; rr++) {
            float4 xv = *(const float4*)(sX + (rgrp * 4 + rr) * 128 + k4 * 4);
#pragma unroll
            for (int cc = 0; cc < 4; cc++) {
                acc[rr][cc] += xv.x * wv[cc].x + xv.y * wv[cc].y
                             + xv.z * wv[cc].z + xv.w * wv[cc].w;
            }
        }
    }

    float bb[4];
#pragma unroll
    for (int cc = 0; cc < 4; cc++) bb[cc] = b[cgrp + 16 * cc];

    float sqp[4] = {0.f, 0.f, 0.f, 0.f};
#pragma unroll
    for (int rr = 0; rr < 4; rr++) {
        int r = i0 + rgrp * 4 + rr;
#pragma unroll
        for (int cc = 0; cc < 4; cc++) {
            float val = acc[rr][cc] + bb[cc];
            out[(size_t)r * 64 + cgrp + 16 * cc] = val;
            sqp[rr] += val * val;
        }
    }
#pragma unroll
    for (int rr = 0; rr < 4; rr++) {
#pragma unroll
        for (int o = 8; o; o >>= 1) sqp[rr] += __shfl_xor_sync(0xffffffffu, sqp[rr], o);
    }
    if (cgrp == 0) {
#pragma unroll
        for (int rr = 0; rr < 4; rr++) g_sq[i0 + rgrp * 4 + rr] = sqp[rr];
    }
}

// ---------------------------------------------------------------------------
// JAX threefry2x32, key (0,1), partitionable counter mode (verified R3).
// ---------------------------------------------------------------------------
__device__ __forceinline__ uint32_t threefry_bits_k01(uint32_t e) {
    const uint32_t ks0 = 0u, ks1 = 1u, ks2 = 0x1BD11BDBu;
    uint32_t x0 = 0u + ks0;
    uint32_t x1 = e + ks1;
#define TF_ROUND(r) { x0 += x1; x1 = __funnelshift_l(x1, x1, (r)); x1 ^= x0; }
    TF_ROUND(13) TF_ROUND(15) TF_ROUND(26) TF_ROUND(6)
    x0 += ks1; x1 += ks2 + 1u;
    TF_ROUND(17) TF_ROUND(29) TF_ROUND(16) TF_ROUND(24)
    x0 += ks2; x1 += ks0 + 2u;
    TF_ROUND(13) TF_ROUND(15) TF_ROUND(26) TF_ROUND(6)
    x0 += ks0; x1 += ks1 + 3u;
    TF_ROUND(17) TF_ROUND(29) TF_ROUND(16) TF_ROUND(24)
    x0 += ks1; x1 += ks2 + 4u;
    TF_ROUND(13) TF_ROUND(15) TF_ROUND(26) TF_ROUND(6)
    x0 += ks2; x1 += ks0 + 5u;
#undef TF_ROUND
    return x0 ^ x1;
}

// Packed dual-FMA (sm_103a f32x2 pipe)
__device__ __forceinline__ void ffma2(unsigned long long& d,
                                      unsigned long long a,
                                      unsigned long long b) {
    asm("fma.rn.f32x2 %0, %1, %2, %0;" : "+l"(d) : "l"(a), "l"(b));
}

// cp.async helpers (LDGSTS): 16B GMEM->SMEM, zero register cost
__device__ __forceinline__ void cp_async16(uint32_t smem_dst, const void* gsrc) {
    asm volatile("cp.async.cg.shared.global [%0], [%1], 16;"
                 :: "r"(smem_dst), "l"(gsrc));
}
__device__ __forceinline__ void cp_async_commit() {
    asm volatile("cp.async.commit_group;");
}
template <int N>
__device__ __forceinline__ void cp_async_wait() {
    asm volatile("cp.async.wait_group %0;" :: "n"(N));
}

// ---------------------------------------------------------------------------
// Fused: pairwise dist + logits + gumbel + top-16 per row.
// Block = (graph g, 32-row i-strip), 256 threads, grid (32, 32), 4 blocks/SM.
// cp.async double-buffered sB; R7-style per-lane merge (known good).
// ---------------------------------------------------------------------------
#define TI 32
#define TJ 64
#define NT (NNODE / TJ)
#define CAP 32
#define SSTRIDE 68    // floats; odd 16B-unit stride -> conflict-free LDS.128
#define THR0 2.8f     // P(any row final 16th < 2.8) ~ 6e-5
#define LGMAX 1.001f

// shared layout in floats
#define SM_SA     0                        // [32][68]        = 2176
#define SM_SB     2176                     // [2][64][68]     = 8704
#define SM_SQI    10880                    // [32]
#define SM_SQJ    10912                    // [2][64]         = 128
#define SM_THR    11040                    // [32]
#define SM_CUTB   11072                    // [32] uint
#define SM_TOPV   11104                    // [32][16]        = 512
#define SM_CANDV  11616                    // [32][32]        = 1024
#define SM_CANDI  12640                    // [32][32] int
#define SM_TOPI   13664                    // [32][16] int
#define SM_CNT    14176                    // [32] int
#define SM_TOTALF 14208
#define SM_BYTES  (SM_TOTALF * 4)          // 56832 B -> 4 blocks/SM

__device__ __forceinline__ uint32_t cut_bits_from_thr(float thr) {
    float fcut = __expf(-__expf(-(thr - LGMAX))) - 2e-7f;
    return __float_as_uint(1.0f + fcut);
}

__global__ void __launch_bounds__(256, 4) dgm_kernel(float* __restrict__ buf,
                                                     const float* __restrict__ tptr) {
    extern __shared__ float sm[];
    float* sA    = sm + SM_SA;
    float* sB    = sm + SM_SB;       // two buffers of 64*SSTRIDE
    float* sqI   = sm + SM_SQI;
    float* sqJ   = sm + SM_SQJ;      // two buffers of 64
    float* thr   = sm + SM_THR;
    uint32_t* cutb = (uint32_t*)(sm + SM_CUTB);
    float* topV  = sm + SM_TOPV;
    float* candV = sm + SM_CANDV;
    int*   candI = (int*)(sm + SM_CANDI);
    int*   topI  = (int*)(sm + SM_TOPI);
    int*   cnt   = (int*)(sm + SM_CNT);

    const float* h = buf;
    int tid = threadIdx.x;
    int g   = blockIdx.x;
    int i0  = blockIdx.y * TI;
    int gbase = g * NNODE;

    // cp.async lane assignment for sB tiles: 1024 16B-chunks / 256 threads = 4
    int pr  = tid >> 2;              // row 0..63
    int pk4 = (tid & 3) * 4;         // k4 group base
    uint32_t sb_smem[2], sq_smem[2];
#pragma unroll
    for (int bb2 = 0; bb2 < 2; bb2++) {
        sb_smem[bb2] = (uint32_t)__cvta_generic_to_shared(
            sB + bb2 * (TJ * SSTRIDE) + pr * SSTRIDE + pk4 * 4);
        sq_smem[bb2] = (uint32_t)__cvta_generic_to_shared(sqJ + bb2 * TJ + (tid & 15) * 4);
    }

    // ---- kick off tile 0 async load into buffer 0 ----
    {
        const float4* src = (const float4*)(h + (size_t)(gbase + pr) * 64);
#pragma unroll
        for (int u = 0; u < 4; u++)
            cp_async16(sb_smem[0] + u * 16, src + pk4 + u);
        if (tid < 16)
            cp_async16(sq_smem[0], g_sq + gbase + (tid & 15) * 4);
        cp_async_commit();
    }

    // ---- init sA strip + state (overlaps tile-0 load) ----
    for (int idx = tid; idx < TI * 16; idx += 256) {
        int r = idx >> 4, k4 = idx & 15;
        *(float4*)(sA + r * SSTRIDE + k4 * 4) =
            ((const float4*)(h + (size_t)(gbase + i0 + r) * 64))[k4];
    }
    if (tid < TI) {
        sqI[tid] = g_sq[gbase + i0 + tid];
        thr[tid] = THR0;
        cutb[tid] = cut_bits_from_thr(THR0);
        cnt[tid] = 0;
    }
    for (int idx = tid; idx < TI * KTOP; idx += 256) { topV[idx] = -INFINITY; topI[idx] = 0; }

    float nT = -(*tptr);
    int tx = tid & 31;      // j-cols: tx + 32*jj, jj in {0,1}
    int ty = tid >> 5;      // i-rows: ty*4 + ii

    for (int jt = 0; jt < NT; jt++) {
        int cur = jt & 1;
        // ---- issue next tile's async load into the other buffer ----
        if (jt + 1 < NT) {
            int jn = (jt + 1) * TJ;
            const float4* src = (const float4*)(h + (size_t)(gbase + jn + pr) * 64);
#pragma unroll
            for (int u = 0; u < 4; u++)
                cp_async16(sb_smem[cur ^ 1] + u * 16, src + pk4 + u);
            if (tid < 16)
                cp_async16(sq_smem[cur ^ 1], g_sq + gbase + jn + (tid & 15) * 4);
            cp_async_commit();
            cp_async_wait<1>();      // current tile's group complete
        } else {
            cp_async_wait<0>();
        }
        __syncthreads();             // staged data visible to all threads

        int j0 = jt * TJ;
        const float* sBc  = sB + cur * (TJ * SSTRIDE);
        const float* sqJc = sqJ + cur * TJ;

        // ---- 4x2 register-tiled dots, packed f32x2 FMA ----
        unsigned long long acc2[4][2];
#pragma unroll
        for (int ii = 0; ii < 4; ii++) { acc2[ii][0] = 0ull; acc2[ii][1] = 0ull; }

        const float* pA = sA + (ty * 4) * SSTRIDE;
        const float* pB = sBc + tx * SSTRIDE;
#pragma unroll
        for (int k4 = 0; k4 < 16; k4++) {
            ulonglong2 b0 = *(const ulonglong2*)(pB + k4 * 4);
            ulonglong2 b1 = *(const ulonglong2*)(pB + 32 * SSTRIDE + k4 * 4);
#pragma unroll
            for (int ii = 0; ii < 4; ii++) {
                ulonglong2 a = *(const ulonglong2*)(pA + ii * SSTRIDE + k4 * 4);
                ffma2(acc2[ii][0], a.x, b0.x);
                ffma2(acc2[ii][0], a.y, b0.y);
                ffma2(acc2[ii][1], a.x, b1.x);
                ffma2(acc2[ii][1], a.y, b1.y);
            }
        }

        // ---- per-row scalars ----
        float thrR[4], sqi[4], sqj[2];
        uint32_t cutM[4];
#pragma unroll
        for (int ii = 0; ii < 4; ii++) {
            thrR[ii] = thr[ty * 4 + ii];
            sqi[ii]  = sqI[ty * 4 + ii];
            cutM[ii] = cutb[ty * 4 + ii] & 0x007fffffu;
        }
        sqj[0] = sqJc[tx];
        sqj[1] = sqJc[32 + tx];

        uint32_t e0 = ((uint32_t)g << 20) + ((uint32_t)(i0 + ty * 4) << 10)
                      + (uint32_t)(j0 + tx);

        // ---- batched hashes + filter ----
        uint32_t bts[8];
#pragma unroll
        for (int u = 0; u < 8; u++) {
            int ii = u >> 1, jj = u & 1;
            bts[u] = threefry_bits_k01(e0 + ((uint32_t)ii << 10) + ((uint32_t)jj << 5));
        }
#pragma unroll
        for (int u = 0; u < 8; u++) {
            int ii = u >> 1, jj = u & 1;
            uint32_t mant = bts[u] >> 9;
            if (mant > cutM[ii]) {
                int li = ty * 4 + ii;
                unsigned long long av = acc2[ii][jj];
                float dot = __uint_as_float((uint32_t)av)
                          + __uint_as_float((uint32_t)(av >> 32));
                float f   = __uint_as_float(mant | 0x3f800000u) - 1.0f;
                float gum = -__logf(-log1pf(f - 1.0f));
                float s   = __fadd_rn(sqi[ii], sqj[jj]);
                float d   = __fadd_rn(s, -__fmul_rn(2.0f, dot));
                float lg  = __expf(__fmul_rn(nT, d));
                float v   = lg + gum;
                if (v > thrR[ii]) {
                    int p = atomicAdd(&cnt[li], 1);
                    if (p < CAP) {
                        candV[li * CAP + p] = v;
                        candI[li * CAP + p] = j0 + jj * 32 + tx;
                    }
                }
            }
        }
        __syncthreads();

        // ---- merge: 32 lanes, one row each (R7-style, known good) ----
        if (tid < TI) {
            int r = tid, c = min(cnt[r], CAP);
            float* tv = topV + r * KTOP;
            int*   ti = topI + r * KTOP;
            for (int m = 0; m < c; m++) {
                float v = candV[r * CAP + m];
                if (v > tv[KTOP - 1]) {
                    int id = candI[r * CAP + m];
                    int p = KTOP - 1;
                    while (p > 0 && tv[p - 1] < v) {
                        tv[p] = tv[p - 1]; ti[p] = ti[p - 1]; p--;
                    }
                    tv[p] = v; ti[p] = id;
                }
            }
            cnt[r] = 0;
            float nthr = fmaxf(tv[KTOP - 1], THR0);
            thr[r] = nthr;
            cutb[r] = cut_bits_from_thr(nthr);
        }
        __syncthreads();
    }

    // ---- write edges (indices as float) ----
    if (tid < TI) {
        int grow = gbase + i0 + tid;
        size_t base = (size_t)grow * KTOP;
        float rowv = (float)grow;
#pragma unroll
        for (int k = 0; k < KTOP; k++) {
            buf[ROWS_OFF + base + k] = rowv;
            buf[COLS_OFF + base + k] = (float)(gbase + topI[tid * KTOP + k]);
        }
    }
}

// ---------------------------------------------------------------------------
extern "C" void kernel_launch(void* const* d_in, const int* in_sizes, int n_in,
                              void* d_out, int out_size) {
    const float* x    = (const float*)d_in[0];
    const float* W    = (const float*)d_in[1];
    const float* b    = (const float*)d_in[2];
    const float* temp = (const float*)d_in[3];
    float* out = (float*)d_out;

    cudaFuncSetAttribute(enc_kernel, cudaFuncAttributeMaxDynamicSharedMemorySize, ENC_BYTES);
    enc_kernel<<<NROWS / 64, 256, ENC_BYTES>>>(x, W, b, out);
    cudaFuncSetAttribute(dgm_kernel, cudaFuncAttributeMaxDynamicSharedMemorySize, SM_BYTES);
    dgm_kernel<<<dim3(NGRAPH, NNODE / TI), 256, SM_BYTES>>>(out, temp);
}

// round 11
// speedup vs baseline: 2.2770x; 1.0039x over previous
#include <cuda_runtime.h>
#include <math.h>
#include <stdint.h>

#define NGRAPH 32
#define NNODE  1024
#define CDIM   64
#define KTOP   16
#define NROWS  (NGRAPH * NNODE)            // 32768
#define OUT_ELEMS (NROWS * CDIM)           // 2097152
#define ROWS_OFF  OUT_ELEMS
#define COLS_OFF  (OUT_ELEMS + NROWS * KTOP)

__device__ float g_sq[NROWS];

// ---------------------------------------------------------------------------
// Encoder + fused row squared-norms.  4x4 register tile, 64-row blocks.
// ---------------------------------------------------------------------------
#define ENC_WT   0
#define ENC_X    8448
#define ENC_TOTF 16640
#define ENC_BYTES (ENC_TOTF * 4)

__global__ void __launch_bounds__(256) enc_kernel(const float* __restrict__ x,
                                                  const float* __restrict__ W,
                                                  const float* __restrict__ b,
                                                  float* __restrict__ out) {
    extern __shared__ float esm[];
    float* sWt = esm + ENC_WT;
    float* sX  = esm + ENC_X;
    int tid = threadIdx.x;
    int i0 = blockIdx.x * 64;

    for (int idx = tid; idx < 128 * 64; idx += 256) {
        int k = idx >> 6, c = idx & 63;
        sWt[c * 132 + k] = W[idx];
    }
    for (int idx = tid; idx < 64 * 128 / 4; idx += 256) {
        ((float4*)sX)[idx] = ((const float4*)(x + (size_t)i0 * 128))[idx];
    }
    __syncthreads();

    int cgrp = tid & 15;
    int rgrp = tid >> 4;
    float acc[4][4];
#pragma unroll
    for (int rr = 0; rr < 4; rr++)
#pragma unroll
        for (int cc = 0; cc < 4; cc++) acc[rr][cc] = 0.f;

#pragma unroll
    for (int k4 = 0; k4 < 32; k4++) {
        float4 wv[4];
#pragma unroll
        for (int cc = 0; cc < 4; cc++)
            wv[cc] = *(const float4*)(sWt + (cgrp + 16 * cc) * 132 + k4 * 4);
#pragma unroll
        for (int rr = 0; rr < 4; rr++) {
            float4 xv = *(const float4*)(sX + (rgrp * 4 + rr) * 128 + k4 * 4);
#pragma unroll
            for (int cc = 0; cc < 4; cc++) {
                acc[rr][cc] += xv.x * wv[cc].x + xv.y * wv[cc].y
                             + xv.z * wv[cc].z + xv.w * wv[cc].w;
            }
        }
    }

    float bb[4];
#pragma unroll
    for (int cc = 0; cc < 4; cc++) bb[cc] = b[cgrp + 16 * cc];

    float sqp[4] = {0.f, 0.f, 0.f, 0.f};
#pragma unroll
    for (int rr = 0; rr < 4; rr++) {
        int r = i0 + rgrp * 4 + rr;
#pragma unroll
        for (int cc = 0; cc < 4; cc++) {
            float val = acc[rr][cc] + bb[cc];
            out[(size_t)r * 64 + cgrp + 16 * cc] = val;
            sqp[rr] += val * val;
        }
    }
#pragma unroll
    for (int rr = 0; rr < 4; rr++) {
#pragma unroll
        for (int o = 8; o; o >>= 1) sqp[rr] += __shfl_xor_sync(0xffffffffu, sqp[rr], o);
    }
    if (cgrp == 0) {
#pragma unroll
        for (int rr = 0; rr < 4; rr++) g_sq[i0 + rgrp * 4 + rr] = sqp[rr];
    }
}

// ---------------------------------------------------------------------------
// JAX threefry2x32, key (0,1), partitionable counter mode (verified R3).
// ---------------------------------------------------------------------------
__device__ __forceinline__ uint32_t threefry_bits_k01(uint32_t e) {
    const uint32_t ks0 = 0u, ks1 = 1u, ks2 = 0x1BD11BDBu;
    uint32_t x0 = 0u + ks0;
    uint32_t x1 = e + ks1;
#define TF_ROUND(r) { x0 += x1; x1 = __funnelshift_l(x1, x1, (r)); x1 ^= x0; }
    TF_ROUND(13) TF_ROUND(15) TF_ROUND(26) TF_ROUND(6)
    x0 += ks1; x1 += ks2 + 1u;
    TF_ROUND(17) TF_ROUND(29) TF_ROUND(16) TF_ROUND(24)
    x0 += ks2; x1 += ks0 + 2u;
    TF_ROUND(13) TF_ROUND(15) TF_ROUND(26) TF_ROUND(6)
    x0 += ks0; x1 += ks1 + 3u;
    TF_ROUND(17) TF_ROUND(29) TF_ROUND(16) TF_ROUND(24)
    x0 += ks1; x1 += ks2 + 4u;
    TF_ROUND(13) TF_ROUND(15) TF_ROUND(26) TF_ROUND(6)
    x0 += ks2; x1 += ks0 + 5u;
#undef TF_ROUND
    return x0 ^ x1;
}

// Packed dual-FMA (sm_103a f32x2 pipe)
__device__ __forceinline__ void ffma2(unsigned long long& d,
                                      unsigned long long a,
                                      unsigned long long b) {
    asm("fma.rn.f32x2 %0, %1, %2, %0;" : "+l"(d) : "l"(a), "l"(b));
}

// cp.async helpers (LDGSTS)
__device__ __forceinline__ void cp_async16(uint32_t smem_dst, const void* gsrc) {
    asm volatile("cp.async.cg.shared.global [%0], [%1], 16;"
                 :: "r"(smem_dst), "l"(gsrc));
}
__device__ __forceinline__ void cp_async_commit() {
    asm volatile("cp.async.commit_group;");
}
template <int N>
__device__ __forceinline__ void cp_async_wait() {
    asm volatile("cp.async.wait_group %0;" :: "n"(N));
}

// ---------------------------------------------------------------------------
// Fused: pairwise dist + logits + gumbel + top-16 per row.
// Block = (graph g, 32-row i-strip), 256 threads, grid (32, 32), 4 blocks/SM.
// Row li = ty*4+ii receives candidates ONLY from warp ty -> candidate state
// is warp-private: merge under __syncwarp, ONE __syncthreads per tile.
// ---------------------------------------------------------------------------
#define TI 32
#define TJ 64
#define NT (NNODE / TJ)
#define CAP 32
#define SSTRIDE 68
#define THR0 2.8f     // P(any row final 16th < 2.8) ~ 6e-5
#define LGMAX 1.001f

// shared layout in floats
#define SM_SA     0                        // [32][68]        = 2176
#define SM_SB     2176                     // [2][64][68]     = 8704
#define SM_SQI    10880                    // [32]
#define SM_SQJ    10912                    // [2][64]         = 128
#define SM_THR    11040                    // [32]
#define SM_CUTB   11072                    // [32] uint
#define SM_TOPV   11104                    // [32][16]        = 512
#define SM_CANDV  11616                    // [32][32]        = 1024
#define SM_CANDI  12640                    // [32][32] int
#define SM_TOPI   13664                    // [32][16] int
#define SM_CNT    14176                    // [32] int
#define SM_TOTALF 14208
#define SM_BYTES  (SM_TOTALF * 4)          // 56832 B -> 4 blocks/SM

__device__ __forceinline__ uint32_t cut_bits_from_thr(float thr) {
    float fcut = __expf(-__expf(-(thr - LGMAX))) - 2e-7f;
    return __float_as_uint(1.0f + fcut);
}

__global__ void __launch_bounds__(256, 4) dgm_kernel(float* __restrict__ buf,
                                                     const float* __restrict__ tptr) {
    extern __shared__ float sm[];
    float* sA    = sm + SM_SA;
    float* sB    = sm + SM_SB;
    float* sqI   = sm + SM_SQI;
    float* sqJ   = sm + SM_SQJ;
    float* thr   = sm + SM_THR;
    uint32_t* cutb = (uint32_t*)(sm + SM_CUTB);
    float* topV  = sm + SM_TOPV;
    float* candV = sm + SM_CANDV;
    int*   candI = (int*)(sm + SM_CANDI);
    int*   topI  = (int*)(sm + SM_TOPI);
    int*   cnt   = (int*)(sm + SM_CNT);

    const float* h = buf;
    int tid = threadIdx.x;
    int g   = blockIdx.x;
    int i0  = blockIdx.y * TI;
    int gbase = g * NNODE;

    int pr  = tid >> 2;              // cp.async row 0..63
    int pk4 = (tid & 3) * 4;
    uint32_t sb_smem[2], sq_smem[2];
#pragma unroll
    for (int bb2 = 0; bb2 < 2; bb2++) {
        sb_smem[bb2] = (uint32_t)__cvta_generic_to_shared(
            sB + bb2 * (TJ * SSTRIDE) + pr * SSTRIDE + pk4 * 4);
        sq_smem[bb2] = (uint32_t)__cvta_generic_to_shared(sqJ + bb2 * TJ + (tid & 15) * 4);
    }

    // ---- kick off tile 0 async load into buffer 0 ----
    {
        const float4* src = (const float4*)(h + (size_t)(gbase + pr) * 64);
#pragma unroll
        for (int u = 0; u < 4; u++)
            cp_async16(sb_smem[0] + u * 16, src + pk4 + u);
        if (tid < 16)
            cp_async16(sq_smem[0], g_sq + gbase + (tid & 15) * 4);
        cp_async_commit();
    }

    // ---- init sA strip + state (overlaps tile-0 load) ----
    for (int idx = tid; idx < TI * 16; idx += 256) {
        int r = idx >> 4, k4 = idx & 15;
        *(float4*)(sA + r * SSTRIDE + k4 * 4) =
            ((const float4*)(h + (size_t)(gbase + i0 + r) * 64))[k4];
    }
    if (tid < TI) {
        sqI[tid] = g_sq[gbase + i0 + tid];
        thr[tid] = THR0;
        cutb[tid] = cut_bits_from_thr(THR0);
        cnt[tid] = 0;
    }
    for (int idx = tid; idx < TI * KTOP; idx += 256) { topV[idx] = -INFINITY; topI[idx] = 0; }

    float nT = -(*tptr);
    int tx = tid & 31;      // j-cols: tx + 32*jj
    int ty = tid >> 5;      // warp; owns rows ty*4 .. ty*4+3

    for (int jt = 0; jt < NT; jt++) {
        int cur = jt & 1;
        cp_async_wait<0>();
        __syncthreads();     // buf[cur] visible; all warps done reading buf[cur^1]

        // ---- issue next tile into the other buffer (overlaps this tile) ----
        if (jt + 1 < NT) {
            int jn = (jt + 1) * TJ;
            const float4* src = (const float4*)(h + (size_t)(gbase + jn + pr) * 64);
#pragma unroll
            for (int u = 0; u < 4; u++)
                cp_async16(sb_smem[cur ^ 1] + u * 16, src + pk4 + u);
            if (tid < 16)
                cp_async16(sq_smem[cur ^ 1], g_sq + gbase + jn + (tid & 15) * 4);
            cp_async_commit();
        }

        int j0 = jt * TJ;
        const float* sBc  = sB + cur * (TJ * SSTRIDE);
        const float* sqJc = sqJ + cur * TJ;

        // ---- 4x2 register-tiled dots, packed f32x2 FMA ----
        unsigned long long acc2[4][2];
#pragma unroll
        for (int ii = 0; ii < 4; ii++) { acc2[ii][0] = 0ull; acc2[ii][1] = 0ull; }

        const float* pA = sA + (ty * 4) * SSTRIDE;
        const float* pB = sBc + tx * SSTRIDE;
#pragma unroll
        for (int k4 = 0; k4 < 16; k4++) {
            ulonglong2 b0 = *(const ulonglong2*)(pB + k4 * 4);
            ulonglong2 b1 = *(const ulonglong2*)(pB + 32 * SSTRIDE + k4 * 4);
#pragma unroll
            for (int ii = 0; ii < 4; ii++) {
                ulonglong2 a = *(const ulonglong2*)(pA + ii * SSTRIDE + k4 * 4);
                ffma2(acc2[ii][0], a.x, b0.x);
                ffma2(acc2[ii][0], a.y, b0.y);
                ffma2(acc2[ii][1], a.x, b1.x);
                ffma2(acc2[ii][1], a.y, b1.y);
            }
        }

        // ---- per-row scalars (owner-warp state: no cross-warp hazard) ----
        float thrR[4], sqi[4], sqj[2];
        uint32_t cutM[4];
#pragma unroll
        for (int ii = 0; ii < 4; ii++) {
            thrR[ii] = thr[ty * 4 + ii];
            sqi[ii]  = sqI[ty * 4 + ii];
            cutM[ii] = cutb[ty * 4 + ii] & 0x007fffffu;
        }
        sqj[0] = sqJc[tx];
        sqj[1] = sqJc[32 + tx];

        uint32_t e0 = ((uint32_t)g << 20) + ((uint32_t)(i0 + ty * 4) << 10)
                      + (uint32_t)(j0 + tx);

        // ---- batched hashes + filter ----
        uint32_t bts[8];
#pragma unroll
        for (int u = 0; u < 8; u++) {
            int ii = u >> 1, jj = u & 1;
            bts[u] = threefry_bits_k01(e0 + ((uint32_t)ii << 10) + ((uint32_t)jj << 5));
        }
#pragma unroll
        for (int u = 0; u < 8; u++) {
            int ii = u >> 1, jj = u & 1;
            uint32_t mant = bts[u] >> 9;
            if (mant > cutM[ii]) {
                int li = ty * 4 + ii;
                unsigned long long av = acc2[ii][jj];
                float dot = __uint_as_float((uint32_t)av)
                          + __uint_as_float((uint32_t)(av >> 32));
                float f   = __uint_as_float(mant | 0x3f800000u) - 1.0f;
                float gum = -__logf(-log1pf(f - 1.0f));
                float s   = __fadd_rn(sqi[ii], sqj[jj]);
                float d   = __fadd_rn(s, -__fmul_rn(2.0f, dot));
                float lg  = __expf(__fmul_rn(nT, d));
                float v   = lg + gum;
                if (v > thrR[ii]) {
                    int p = atomicAdd(&cnt[li], 1);
                    if (p < CAP) {
                        candV[li * CAP + p] = v;
                        candI[li * CAP + p] = j0 + jj * 32 + tx;
                    }
                }
            }
        }

        // ---- warp-private merge: lanes 0-3 each merge one owned row ----
        __syncwarp();
        if (tx < 4) {
            int r = ty * 4 + tx;
            int c = min(cnt[r], CAP);
            float* tv = topV + r * KTOP;
            int*   ti = topI + r * KTOP;
            for (int m = 0; m < c; m++) {
                float v = candV[r * CAP + m];
                if (v > tv[KTOP - 1]) {
                    int id = candI[r * CAP + m];
                    int p = KTOP - 1;
                    while (p > 0 && tv[p - 1] < v) {
                        tv[p] = tv[p - 1]; ti[p] = ti[p - 1]; p--;
                    }
                    tv[p] = v; ti[p] = id;
                }
            }
            cnt[r] = 0;
            float nthr = fmaxf(tv[KTOP - 1], THR0);
            thr[r] = nthr;
            cutb[r] = cut_bits_from_thr(nthr);
        }
        __syncwarp();
    }

    __syncthreads();   // all warps' topI final before cross-warp read

    // ---- write edges (indices as float) ----
    if (tid < TI) {
        int grow = gbase + i0 + tid;
        size_t base = (size_t)grow * KTOP;
        float rowv = (float)grow;
#pragma unroll
        for (int k = 0; k < KTOP; k++) {
            buf[ROWS_OFF + base + k] = rowv;
            buf[COLS_OFF + base + k] = (float)(gbase + topI[tid * KTOP + k]);
        }
    }
}

// ---------------------------------------------------------------------------
extern "C" void kernel_launch(void* const* d_in, const int* in_sizes, int n_in,
                              void* d_out, int out_size) {
    const float* x    = (const float*)d_in[0];
    const float* W    = (const float*)d_in[1];
    const float* b    = (const float*)d_in[2];
    const float* temp = (const float*)d_in[3];
    float* out = (float*)d_out;

    cudaFuncSetAttribute(enc_kernel, cudaFuncAttributeMaxDynamicSharedMemorySize, ENC_BYTES);
    enc_kernel<<<NROWS / 64, 256, ENC_BYTES>>>(x, W, b, out);
    cudaFuncSetAttribute(dgm_kernel, cudaFuncAttributeMaxDynamicSharedMemorySize, SM_BYTES);
    dgm_kernel<<<dim3(NGRAPH, NNODE / TI), 256, SM_BYTES>>>(out, temp);
}